// round 11
// baseline (speedup 1.0000x reference)
#include <cuda_runtime.h>
#include <cuda_bf16.h>

#define NN 16384      // nodes/edges (and bond_n rows A = 16384)
#define DD 128        // emb dim
// Only layer i = 2 matters: the reference loop does not feed h back.

#define RSPLIT 9088   // stream blocks: rows [0,9088); GEMM blocks: [9088,16384)

// Scratch (device globals — zero-initialized at module load)
__device__ float g_colw0[NN];                // slot0 column partials (stream blocks)
__device__ float g_hn[(size_t)NN * DD];      // 8 MB (read by k_out)
__device__ float g_mpart[128][DD];           // m partials, one per GEMM block
__device__ unsigned g_flag[128];             // slot0-ready flags (k_out resets)

// ---------------------------------------------------------------------------
// Column-slice partial sum: cols [slice*128, +128), rows [r0, r1), warp-strided.
// (r1-r0) must be divisible by 128. Result (128 sums) -> dst[0..128).
// part[] scratch = sm[0..1024) floats.
// ---------------------------------------------------------------------------
__device__ __forceinline__ void colsum_slice(
    const float* __restrict__ bn, float* sm, int slice, int r0, int r1,
    float* dst, int tid)
{
    const int lane = tid & 31, warp = tid >> 5;
    const float* base = bn + (size_t)(r0 + warp) * NN + slice * 128 + lane * 4;
    const int iters = (r1 - r0) >> 3;              // per-warp row count
    float4 a0 = {0,0,0,0}, a1 = {0,0,0,0}, a2 = {0,0,0,0}, a3 = {0,0,0,0};
    for (int i = 0; i < iters; i += 16) {
#pragma unroll
        for (int u = 0; u < 16; u++) {
            float4 v = __ldcs((const float4*)(base + (size_t)(i + u) * 8 * NN));
            float4& a = (u & 3) == 0 ? a0 : (u & 3) == 1 ? a1 : (u & 3) == 2 ? a2 : a3;
            a.x += v.x; a.y += v.y; a.z += v.z; a.w += v.w;
        }
    }
    float sx = a0.x + a1.x + a2.x + a3.x;
    float sy = a0.y + a1.y + a2.y + a3.y;
    float sz = a0.z + a1.z + a2.z + a3.z;
    float sw = a0.w + a1.w + a2.w + a3.w;
    float* part = sm;                               // [8][128] = 4 KB
    __syncthreads();                                // sm may be dirty
    part[warp * 128 + lane * 4 + 0] = sx;
    part[warp * 128 + lane * 4 + 1] = sy;
    part[warp * 128 + lane * 4 + 2] = sz;
    part[warp * 128 + lane * 4 + 3] = sw;
    __syncthreads();
    if (tid < 128) {
        float s = 0.f;
#pragma unroll
        for (int w = 0; w < 8; w++) s += part[w * 128 + tid];
        dst[tid] = s;
    }
    __syncthreads();
}

// ---------------------------------------------------------------------------
// k_fused, 256 blocks (one wave @ 2/SM, all co-resident -> pairwise wait safe):
//   blocks [0,128):   colsum slice=bid rows [0,RSPLIT) -> g_colw0 + flag.
//   blocks [128,256): GEMM h_n (parked in SMEM + written to g_hn), then
//                     colsum slice=bid-128 rows [RSPLIT,NN) kept in SMEM,
//                     wait partner flag, colw = slot0+slot1, m-partial from
//                     SMEM h_n -> g_mpart. No atomics; deterministic.
// ---------------------------------------------------------------------------
__global__ void __launch_bounds__(256, 2) k_fused(
    const float* __restrict__ bn,
    const int* __restrict__ x, const int* __restrict__ ea,
    const float* __restrict__ aemb, const float* __restrict__ bemb,
    const float* __restrict__ Wi_w2, const float* __restrict__ Wi_b2)
{
    extern __shared__ float sm[];                   // 69,632 B dynamic
    __shared__ float red[256];
    __shared__ float colw1[128];
    __shared__ float bias_s[128];
    __shared__ int xi0[128], xi1[128], ei0[128], ei1[128];

    const int tid = threadIdx.x;
    const int bid = blockIdx.x;

    if (bid < 128) {
        // ---------------- stream path ----------------
        float out_s[1];
        colsum_slice(bn, sm, bid, 0, RSPLIT, red, tid);   // red[0..128) = slot0
        (void)out_s;
        if (tid < 128) g_colw0[bid * 128 + tid] = red[tid];
        __threadfence();
        __syncthreads();
        if (tid == 0) *((volatile unsigned*)&g_flag[bid]) = 1u;
        return;
    }

    // ---------------- GEMM path (blocks 128..255) ----------------
    {
        float* w_s   = sm;                 // [64][129] = 33,024 B (per-k chunk)
        float* cat_s = sm + 64 * 129;      // [128][64] = 32,768 B
        const int rowBase = (bid - 128) * 128;

        if (tid < 128) {
            bias_s[tid] = Wi_b2[tid];
            int r = rowBase + tid;
            xi0[tid] = x[2 * r];  xi1[tid] = x[2 * r + 1];
            ei0[tid] = ea[2 * r]; ei1[tid] = ea[2 * r + 1];
        }
        __syncthreads();

        const int tx = tid & 15, ty = tid >> 4;
        float acc[8][8];
#pragma unroll
        for (int i = 0; i < 8; i++)
#pragma unroll
            for (int j = 0; j < 8; j++) acc[i][j] = 0.f;

        for (int kc = 0; kc < 256; kc += 64) {
            for (int idx = tid; idx < 8192; idx += 256) {
                int d = idx >> 6, kk = idx & 63;
                w_s[kk * 129 + d] = Wi_w2[d * 256 + kc + kk];
            }
            const bool atom = (kc < 128);
            const float* emb = atom ? aemb : bemb;
            for (int idx = tid; idx < 2048; idx += 256) {
                int row  = idx >> 4;
                int kloc = (idx & 15) * 4;
                int i0 = atom ? xi0[row] : ei0[row];
                int i1 = atom ? xi1[row] : ei1[row];
                int ko = atom ? (kc + kloc) : (kc - 128 + kloc);
                float4 v0 = *(const float4*)(emb + i0 * 128 + ko);
                float4 v1 = *(const float4*)(emb + i1 * 128 + ko);
                float4 s;
                s.x = v0.x + v1.x; s.y = v0.y + v1.y;
                s.z = v0.z + v1.z; s.w = v0.w + v1.w;
                *(float4*)(cat_s + row * 64 + kloc) = s;
            }
            __syncthreads();

#pragma unroll 8
            for (int kk = 0; kk < 64; kk++) {
                const float* wr = w_s + kk * 129;
                float b[8], a[8];
#pragma unroll
                for (int j = 0; j < 8; j++) b[j] = wr[tx + 16 * j];
#pragma unroll
                for (int i = 0; i < 8; i++) a[i] = cat_s[(ty + 16 * i) * 64 + kk];
#pragma unroll
                for (int i = 0; i < 8; i++)
#pragma unroll
                    for (int j = 0; j < 8; j++)
                        acc[i][j] = fmaf(a[i], b[j], acc[i][j]);
            }
            __syncthreads();
        }

        // bias + relu -> g_hn AND parked in SMEM at sm+1024 (bytes [4096,69632))
        float* hn_s = sm + 1024;
#pragma unroll
        for (int i = 0; i < 8; i++) {
            int r = ty + 16 * i;
#pragma unroll
            for (int j = 0; j < 8; j++) {
                int d = tx + 16 * j;
                float v = acc[i][j] + bias_s[d];
                v = v > 0.f ? v : 0.f;
                g_hn[(size_t)(rowBase + r) * 128 + d] = v;
                hn_s[r * 128 + d] = v;
            }
        }
        __syncthreads();
    }

    // colsum tail: bottom rows of the paired slice -> colw1 (SMEM only)
    colsum_slice(bn, sm, bid - 128, RSPLIT, NN, colw1, tid);

    // wait for partner's slot0 (pairwise; both finish streaming ~together)
    if (tid == 0) {
        volatile unsigned* f = &g_flag[bid - 128];
        while (*f == 0u) __nanosleep(64);
    }
    __syncthreads();
    __threadfence();
    if (tid < 128) colw1[tid] += __ldcg(&g_colw0[(bid - 128) * 128 + tid]);
    __syncthreads();

    // m-partial from SMEM h_n: p[d] = sum_r colw[r] * hn[r,d]
    {
        const float* hn_s = sm + 1024;
        const int d = tid & 127, half = tid >> 7;
        float p = 0.f;
#pragma unroll 8
        for (int r = 0; r < 64; r++) {
            int row = half * 64 + r;
            p = fmaf(colw1[row], hn_s[row * 128 + d], p);
        }
        red[tid] = p;
    }
    __syncthreads();
    if (tid < 128) g_mpart[bid - 128][tid] = red[tid] + red[tid + 128];
}

// ---------------------------------------------------------------------------
// k_out, 256 blocks x 256 threads (64 h_n rows each):
//   redundant per-block: m = sum of 128 partials (64 KB, L2-hot), then
//   mm = m @ Wm^T + b; then out = relu(h_n + mm) for own rows.
//   Block 0 also resets g_flag for the next graph replay.
// ---------------------------------------------------------------------------
__global__ void __launch_bounds__(256) k_out(const float* __restrict__ Wm_w2,
                                             const float* __restrict__ Wm_b2,
                                             float* __restrict__ out) {
    __shared__ float red[256];
    __shared__ float ms[128];
    __shared__ float mm_s[128];

    const int bid = blockIdx.x, tid = threadIdx.x;
    const int d = tid & 127, half = tid >> 7;

    if (bid == 0 && tid < 128) g_flag[tid] = 0u;   // reset for next replay

    // m reduce: halves take alternating partials (64 strided loads each)
    {
        float s = 0.f;
#pragma unroll 16
        for (int p = half; p < 128; p += 2) s += g_mpart[p][d];
        red[tid] = s;
    }
    __syncthreads();
    if (tid < 128) ms[tid] = red[tid] + red[tid + 128];
    __syncthreads();

    if (tid < 128) {
        float s = Wm_b2[tid];
        const float* row = Wm_w2 + tid * 128;
#pragma unroll 8
        for (int k = 0; k < 128; k++) s = fmaf(ms[k], __ldg(row + k), s);
        mm_s[tid] = s;
    }
    __syncthreads();

    // out = relu(h_n + mm) for rows [bid*64, +64): 2048 float4
    {
        const float* hn = g_hn + (size_t)bid * 64 * 128;
        float4* ob = (float4*)(out + (size_t)bid * 64 * 128);
#pragma unroll 4
        for (int i = tid; i < 2048; i += 256) {
            int row = i >> 5, dg = (i & 31) * 4;
            float4 v = *(const float4*)(hn + row * 128 + dg);
            v.x = fmaxf(v.x + mm_s[dg + 0], 0.f);
            v.y = fmaxf(v.y + mm_s[dg + 1], 0.f);
            v.z = fmaxf(v.z + mm_s[dg + 2], 0.f);
            v.w = fmaxf(v.w + mm_s[dg + 3], 0.f);
            ob[i] = v;
        }
    }
}

// ---------------------------------------------------------------------------
extern "C" void kernel_launch(void* const* d_in, const int* in_sizes, int n_in,
                              void* d_out, int out_size) {
    const int*   x    = (const int*)d_in[0];
    const int*   ea   = (const int*)d_in[1];
    const float* bn   = (const float*)d_in[2];
    const float* aemb = (const float*)d_in[3];
    const float* bemb = (const float*)d_in[4];
    const float* Wi_w = (const float*)d_in[5];
    const float* Wi_b = (const float*)d_in[6];
    const float* Wm_w = (const float*)d_in[7];
    const float* Wm_b = (const float*)d_in[8];

    // Only the last layer (i = 2) affects the output.
    const float* Wi_w2 = Wi_w + 2 * 128 * 256;
    const float* Wi_b2 = Wi_b + 2 * 128;
    const float* Wm_w2 = Wm_w + 2 * 128 * 128;
    const float* Wm_b2 = Wm_b + 2 * 128;

    const int smem = 69632;   // 1024-float colsum scratch + 128x128 h_n park
    static bool attr_set = false;
    if (!attr_set) {
        cudaFuncSetAttribute(k_fused, cudaFuncAttributeMaxDynamicSharedMemorySize, smem);
        attr_set = true;
    }

    k_fused<<<256, 256, smem>>>(bn, x, ea, aemb, bemb, Wi_w2, Wi_b2);
    k_out<<<256, 256>>>(Wm_w2, Wm_b2, (float*)d_out);
}